// round 13
// baseline (speedup 1.0000x reference)
#include <cuda_runtime.h>
#include <math.h>
#include <stdint.h>

#define BSZ  512
#define TLEN 64
#define XDIM 512
#define EDIM 1024
#define UDIM 1024
#define NBX_ATT 4

#define TM 128
#define TN 256
#define TK 32
#define NSTAGE 4

#if defined(__CUDA_ARCH_FEAT_SM103_ALL) || defined(__CUDA_ARCH_FEAT_SM100_ALL) || defined(__CUDA_ARCH_FEAT_SM101_ALL)
#define HAS_TCGEN05 1
#else
#define HAS_TCGEN05 0
#endif

// ---------------- static scratch ----------------
__device__ float g_tanhE [(size_t)BSZ * TLEN * EDIM];   // tf32 tanh(E)
__device__ float g_tanh_h[(size_t)BSZ * UDIM];          // tf32 tanh(h)
__device__ float g_h32   [(size_t)BSZ * UDIM];          // tf32 h
__device__ float g_x     [(size_t)BSZ * (XDIM + EDIM)]; // tf32 [inputs | c_t]
__device__ float g_hWa   [(size_t)BSZ * UDIM];
__device__ float g_epart [(size_t)BSZ * TLEN * NBX_ATT];
__device__ float g_G2    [(size_t)BSZ * 2 * UDIM];      // h @ rker[:, :2048]
__device__ float g_G1hh  [(size_t)BSZ * UDIM];          // x@kh + bh
__device__ float g_z     [(size_t)BSZ * UDIM];
__device__ float g_rh    [(size_t)BSZ * UDIM];          // tf32(r*h)
// K-major transposed, tf32-rounded weights: W_T[n][k]
__device__ float g_WaT_lo[(size_t)UDIM * UDIM];
__device__ float g_WaT_hi[(size_t)UDIM * UDIM];
__device__ float g_kernT [(size_t)3 * UDIM * (XDIM + EDIM)];
__device__ float g_rkerT [(size_t)3 * UDIM * UDIM];

__device__ __forceinline__ uint32_t f2tf32(float f) {
    uint32_t r;
    asm("cvt.rna.tf32.f32 %0, %1;" : "=r"(r) : "f"(f));
    return r;
}
__device__ __forceinline__ float tf32r(float f) { return __uint_as_float(f2tf32(f)); }
__device__ __forceinline__ float hsig(float x) { return fminf(fmaxf(0.2f * x + 0.5f, 0.f), 1.f); }

// ---------------- PTX helpers (sm_103a branch only) ----------------
#if HAS_TCGEN05
__device__ __forceinline__ uint32_t smem_u32(const void* p) {
    uint32_t a;
    asm("{ .reg .u64 t; cvta.to.shared.u64 t, %1; cvt.u32.u64 %0, t; }" : "=r"(a) : "l"(p));
    return a;
}
#define SW128(x) ((x) ^ (((x) >> 3) & 0x70))
#define TCG_ALLOC(sm, n)  asm volatile("tcgen05.alloc.cta_group::1.sync.aligned.shared::cta.b32 [%0], %1;" :: "r"(sm), "r"(n) : "memory")
#define TCG_DEALLOC(t, n) asm volatile("tcgen05.dealloc.cta_group::1.sync.aligned.b32 %0, %1;" :: "r"(t), "r"(n))
#define TCG_RELINQ()      asm volatile("tcgen05.relinquish_alloc_permit.cta_group::1.sync.aligned;")
#define TCG_COMMIT(mb)    asm volatile("tcgen05.commit.cta_group::1.mbarrier::arrive::one.shared::cluster.b64 [%0];" :: "r"(mb) : "memory")
#define TCG_FENCE_AFTER() asm volatile("tcgen05.fence::after_thread_sync;" ::: "memory")
#define TCG_FENCE_BEFORE() asm volatile("tcgen05.fence::before_thread_sync;" ::: "memory")
#define TCG_WAIT_LD()     asm volatile("tcgen05.wait::ld.sync.aligned;" ::: "memory")
#define FENCE_ASYNC()     asm volatile("fence.proxy.async.shared::cta;" ::: "memory")
#define MBAR_INIT(mb, c)  asm volatile("mbarrier.init.shared.b64 [%0], %1;" :: "r"(mb), "r"(c) : "memory")
#define CP_ASYNC16(dst, src) asm volatile("cp.async.cg.shared.global [%0], [%1], 16;" :: "r"(dst), "l"(src) : "memory")
#define CP_COMMIT()       asm volatile("cp.async.commit_group;" ::: "memory")

__device__ __forceinline__ void mbar_wait(uint32_t mb, uint32_t parity) {
    uint32_t done;
    asm volatile("{\n\t.reg .pred p;\n\t"
        "mbarrier.try_wait.parity.acquire.cta.shared::cta.b64 p, [%1], %2;\n\t"
        "selp.b32 %0, 1, 0, p;\n\t}"
        : "=r"(done) : "r"(mb), "r"(parity) : "memory");
    if (!done) {
        asm volatile("{\n\t.reg .pred P1;\n\t"
            "W_%=:\n\t"
            "mbarrier.try_wait.parity.acquire.cta.shared::cta.b64 P1, [%0], %1, 0x989680;\n\t"
            "@P1 bra.uni D_%=;\n\t"
            "bra.uni W_%=;\n\t"
            "D_%=:\n\t}"
            :: "r"(mb), "r"(parity) : "memory");
    }
}
__device__ __forceinline__ void mma_tf32_ss(uint32_t d, uint64_t ad, uint64_t bd,
                                            uint32_t idesc, uint32_t acc) {
    asm volatile("{\n\t.reg .pred p;\n\t"
        "setp.ne.u32 p, %5, 0;\n\t"
        "tcgen05.mma.cta_group::1.kind::tf32 [%0], %1, %2, %3, {%4, %4, %4, %4}, p;\n\t}"
        :: "r"(d), "l"(ad), "l"(bd), "r"(idesc), "r"(0u), "r"(acc) : "memory");
}
__device__ __forceinline__ void tmem_ld32(uint32_t* r, uint32_t a) {
    asm volatile("tcgen05.ld.sync.aligned.32x32b.x32.b32 "
        "{%0,%1,%2,%3,%4,%5,%6,%7,%8,%9,%10,%11,%12,%13,%14,%15,"
        "%16,%17,%18,%19,%20,%21,%22,%23,%24,%25,%26,%27,%28,%29,%30,%31}, [%32];"
        : "=r"(r[0]),"=r"(r[1]),"=r"(r[2]),"=r"(r[3]),"=r"(r[4]),"=r"(r[5]),"=r"(r[6]),"=r"(r[7]),
          "=r"(r[8]),"=r"(r[9]),"=r"(r[10]),"=r"(r[11]),"=r"(r[12]),"=r"(r[13]),"=r"(r[14]),"=r"(r[15]),
          "=r"(r[16]),"=r"(r[17]),"=r"(r[18]),"=r"(r[19]),"=r"(r[20]),"=r"(r[21]),"=r"(r[22]),"=r"(r[23]),
          "=r"(r[24]),"=r"(r[25]),"=r"(r[26]),"=r"(r[27]),"=r"(r[28]),"=r"(r[29]),"=r"(r[30]),"=r"(r[31])
        : "r"(a));
}
__device__ __forceinline__ uint64_t mk_desc(uint32_t addr) {
    const uint64_t base = (uint64_t(2) << 61) | (uint64_t(1) << 46)
                        | (uint64_t(64) << 32) | (uint64_t(1) << 16);
    return base | ((uint64_t)(addr >> 4) & 0x3FFF);
}
#endif // HAS_TCGEN05

// ---------------- tanh(E), tf32-rounded ----------------
__global__ void tanh4_kernel(const float4* __restrict__ in, float4* __restrict__ out, int n4)
{
    int i = blockIdx.x * blockDim.x + threadIdx.x;
    if (i < n4) {
        float4 v = in[i];
        uint4 u = make_uint4(f2tf32(tanhf(v.x)), f2tf32(tanhf(v.y)),
                             f2tf32(tanhf(v.z)), f2tf32(tanhf(v.w)));
        *reinterpret_cast<uint4*>(&out[i]) = u;
    }
}

// ---------------- prep: tf32(h), tf32(tanh h), g_x[:, :512] ----------------
__global__ void prep_kernel(const float* __restrict__ h, const float* __restrict__ inputs)
{
    const int idx = blockIdx.x * blockDim.x + threadIdx.x;
    if (idx < BSZ * UDIM) {
        float v = h[idx];
        g_h32[idx]    = tf32r(v);
        g_tanh_h[idx] = tf32r(tanhf(v));
    }
    if (idx < BSZ * XDIM) {
        const int m = idx >> 9, j = idx & 511;
        g_x[(size_t)m * (XDIM + EDIM) + j] = tf32r(inputs[idx]);
    }
}

// ---------------- fused weight transposes, tf32-rounded ----------------
__global__ __launch_bounds__(256)
void transpose_all_kernel(const float* __restrict__ Wa, const float* __restrict__ kern,
                          const float* __restrict__ rker)
{
    const int bid = blockIdx.x;
    const float* src; float* dst; int ld, K, nb, kb;
    if (bid < 1024)      { src = Wa;                     dst = g_WaT_lo; ld = 1024; K = 1024; nb = bid & 31;  kb = bid >> 5; }
    else if (bid < 2048) { int b = bid - 1024; src = Wa + 1024 * 1024; dst = g_WaT_hi; ld = 1024; K = 1024; nb = b & 31; kb = b >> 5; }
    else if (bid < 6656) { int b = bid - 2048; src = kern; dst = g_kernT; ld = 3072; K = 1536; nb = b % 96; kb = b / 96; }
    else                 { int b = bid - 6656; src = rker; dst = g_rkerT; ld = 3072; K = 1024; nb = b % 96; kb = b / 96; }

    __shared__ float t[32][33];
    const int tx = threadIdx.x, ty = threadIdx.y;
    const int n0 = nb * 32, k0 = kb * 32;
    #pragma unroll
    for (int i = 0; i < 32; i += 8)
        t[ty + i][tx] = src[(size_t)(k0 + ty + i) * ld + n0 + tx];
    __syncthreads();
    #pragma unroll
    for (int i = 0; i < 32; i += 8)
        dst[(size_t)(n0 + ty + i) * K + k0 + tx] = tf32r(t[tx][ty + i]);
}

// ---------------- GEMM: 128x256 tile, cp.async 4-stage pipeline (R10-proven) ----------------
enum { EP_STORE = 0, EP_ATT = 2, EP_G1 = 3, EP_GRU = 4 };

#define SM_STAGE_BYTES 49152
#define SM_CTRL (NSTAGE * SM_STAGE_BYTES)
#define SM_TOTAL (SM_CTRL + 64)

template<int EMODE>
__global__ __launch_bounds__(256)
void tgemm_kernel(const float* __restrict__ A, int lda,
                  const float* __restrict__ Bt, int ldb, int nK,
                  float* __restrict__ C, int ldc,
                  const float* __restrict__ hWa, const float* __restrict__ Va,
                  const float* __restrict__ bias,
                  const float* __restrict__ hraw, float* __restrict__ outp)
{
    extern __shared__ char smc[];
    const int tid = threadIdx.x;
    const int row0 = blockIdx.y * TM;
    const int col0 = blockIdx.x * TN;

#if HAS_TCGEN05
    const uint32_t sb  = smem_u32(smc);
    const int wid = tid >> 5;
    const int lid = tid & 31;

    if (wid == 0) { TCG_ALLOC(sb + SM_CTRL, TN); TCG_RELINQ(); }
    if (tid == 0) {
        #pragma unroll
        for (int s = 0; s < NSTAGE; ++s) MBAR_INIT(sb + SM_CTRL + 8 + 8 * s, 1);
    }
    __syncthreads();
    uint32_t tmem;
    asm volatile("ld.shared.b32 %0, [%1];" : "=r"(tmem) : "r"(sb + SM_CTRL));

    const uint32_t idesc = (1u << 4) | (2u << 7) | (2u << 10)
                         | ((TN / 8) << 17) | ((TM / 16) << 24);

    int ar[4], aq[4], br8[8], bq8[8];
    #pragma unroll
    for (int i = 0; i < 4; ++i) { const int s = i * 256 + tid; ar[i] = s >> 3; aq[i] = s & 7; }
    #pragma unroll
    for (int i = 0; i < 8; ++i) { const int s = i * 256 + tid; br8[i] = s >> 3; bq8[i] = s & 7; }

    uint32_t phbits = 0;
    const int itMax = nK + NSTAGE - 1;
    for (int it = 0; it < itMax; ++it) {
        if (it < nK) {
            const int s = it & (NSTAGE - 1);
            if (it >= NSTAGE) {
                mbar_wait(sb + SM_CTRL + 8 + 8 * s, (phbits >> s) & 1u);
                phbits ^= 1u << s;
            }
            const int k0 = it * TK;
            const uint32_t sA = sb + s * SM_STAGE_BYTES;
            const uint32_t sB = sA + 16384;
            #pragma unroll
            for (int i = 0; i < 4; ++i)
                CP_ASYNC16(sA + SW128(ar[i] * 128 + aq[i] * 16),
                           &A[(size_t)(row0 + ar[i]) * lda + k0 + aq[i] * 4]);
            #pragma unroll
            for (int i = 0; i < 8; ++i)
                CP_ASYNC16(sB + SW128(br8[i] * 128 + bq8[i] * 16),
                           &Bt[(size_t)(col0 + br8[i]) * ldb + k0 + bq8[i] * 4]);
        }
        CP_COMMIT();
        const int j = it - (NSTAGE - 1);
        if (j >= 0) {
            asm volatile("cp.async.wait_group %0;" :: "n"(NSTAGE - 1) : "memory");
            __syncthreads();
            if (tid == 0) {
                FENCE_ASYNC();
                const int s = j & (NSTAGE - 1);
                const uint64_t ad = mk_desc(sb + s * SM_STAGE_BYTES);
                const uint64_t bd = mk_desc(sb + s * SM_STAGE_BYTES + 16384);
                #pragma unroll
                for (int ss = 0; ss < 4; ++ss)
                    mma_tf32_ss(tmem, ad + ss * 2, bd + ss * 2, idesc, (j > 0 || ss > 0) ? 1u : 0u);
                TCG_COMMIT(sb + SM_CTRL + 8 + 8 * s);
            }
        }
    }
    {
        const int sl = (nK - 1) & (NSTAGE - 1);
        mbar_wait(sb + SM_CTRL + 8 + 8 * sl, (phbits >> sl) & 1u);
    }
    TCG_FENCE_AFTER();

    // ---- epilogue: 8 warps, two column halves ----
    const int sp = wid & 3;
    const int hf = wid >> 2;
    const int m  = row0 + sp * 32 + lid;

    if (EMODE == EP_ATT) {
        const int b = m >> 6;
        const float* hrow = hWa + (size_t)b * UDIM;
        float s = 0.f;
        #pragma unroll
        for (int c = 0; c < 4; ++c) {
            const int cc = hf * 4 + c;
            uint32_t regs[32];
            tmem_ld32(regs, tmem + cc * 32);
            TCG_WAIT_LD();
            const int jj0 = col0 + cc * 32;
            #pragma unroll
            for (int j2 = 0; j2 < 32; ++j2)
                s += tanhf(__uint_as_float(regs[j2]) + hrow[jj0 + j2]) * Va[jj0 + j2];
        }
        float* sm = reinterpret_cast<float*>(smc);
        __syncthreads();
        sm[wid * 32 + lid] = s;
        __syncthreads();
        if (wid < 4)
            C[(size_t)m * NBX_ATT + blockIdx.x] = sm[wid * 32 + lid] + sm[(wid + 4) * 32 + lid];
    } else if (EMODE == EP_STORE) {
        #pragma unroll
        for (int c = 0; c < 4; ++c) {
            const int cc = hf * 4 + c;
            uint32_t regs[32];
            tmem_ld32(regs, tmem + cc * 32);
            TCG_WAIT_LD();
            const int jj0 = col0 + cc * 32;
            #pragma unroll
            for (int j2 = 0; j2 < 32; j2 += 4) {
                float4 o;
                o.x = __uint_as_float(regs[j2 + 0]);
                o.y = __uint_as_float(regs[j2 + 1]);
                o.z = __uint_as_float(regs[j2 + 2]);
                o.w = __uint_as_float(regs[j2 + 3]);
                *reinterpret_cast<float4*>(&C[(size_t)m * ldc + jj0 + j2]) = o;
            }
        }
    } else if (EMODE == EP_G1) {
        // G1 = x@kern; fused gates. Requires g_G2 already written.
        #pragma unroll
        for (int c = 0; c < 4; ++c) {
            const int cc = hf * 4 + c;
            uint32_t regs[32];
            tmem_ld32(regs, tmem + cc * 32);
            TCG_WAIT_LD();
            const int jj0 = col0 + cc * 32;
            #pragma unroll
            for (int j2 = 0; j2 < 32; ++j2) {
                const int jg = jj0 + j2;
                const float o = __uint_as_float(regs[j2]) + bias[jg];
                if (jg < 1024) {
                    g_z[(size_t)m * UDIM + jg] = hsig(o + g_G2[(size_t)m * 2048 + jg]);
                } else if (jg < 2048) {
                    const int jj = jg - 1024;
                    const float r = hsig(o + g_G2[(size_t)m * 2048 + jg]);
                    g_rh[(size_t)m * UDIM + jj] = tf32r(r * hraw[(size_t)m * UDIM + jj]);
                } else {
                    g_G1hh[(size_t)m * UDIM + jg - 2048] = o;
                }
            }
        }
    } else { // EP_GRU: Ghh = (r*h)@rh; fused h_new -> outp
        #pragma unroll
        for (int c = 0; c < 4; ++c) {
            const int cc = hf * 4 + c;
            uint32_t regs[32];
            tmem_ld32(regs, tmem + cc * 32);
            TCG_WAIT_LD();
            const int jj0 = col0 + cc * 32;
            #pragma unroll
            for (int j2 = 0; j2 < 32; ++j2) {
                const int jg = jj0 + j2;
                const float hh = tanhf(g_G1hh[(size_t)m * UDIM + jg] + __uint_as_float(regs[j2]));
                const float z  = g_z[(size_t)m * UDIM + jg];
                outp[(size_t)m * 1088 + 64 + jg] =
                    z * hraw[(size_t)m * UDIM + jg] + (1.f - z) * hh;
            }
        }
    }
    TCG_FENCE_BEFORE();
    __syncthreads();
    if (wid == 0) TCG_DEALLOC(tmem, TN);

#else
    // ============ FFMA fallback (plain-sm_103 pass; dead code on GB300) ============
    float* Bs = reinterpret_cast<float*>(smc);
    const int Ktot = nK * TK;
    const int m = row0 + (tid & 127);
    float s_att = 0.f;

    for (int nc = 0; nc < 4; ++nc) {
        float acc[64];
        #pragma unroll
        for (int j = 0; j < 64; ++j) acc[j] = 0.f;
        for (int kt = 0; kt < Ktot; kt += 32) {
            for (int i = tid; i < 32 * 64; i += 256) {
                const int kk = i & 31, j = i >> 5;
                Bs[kk * 64 + j] = Bt[(size_t)(col0 + nc * 64 + j) * ldb + kt + kk];
            }
            __syncthreads();
            if (tid < 128) {
                float av[32];
                #pragma unroll
                for (int q = 0; q < 32; q += 4) {
                    float4 v = *reinterpret_cast<const float4*>(&A[(size_t)m * lda + kt + q]);
                    av[q] = v.x; av[q + 1] = v.y; av[q + 2] = v.z; av[q + 3] = v.w;
                }
                #pragma unroll 4
                for (int kk = 0; kk < 32; ++kk) {
                    const float a = av[kk];
                    #pragma unroll
                    for (int j = 0; j < 64; ++j)
                        acc[j] = fmaf(a, Bs[kk * 64 + j], acc[j]);
                }
            }
            __syncthreads();
        }
        if (tid < 128) {
            const int jj0 = col0 + nc * 64;
            for (int j = 0; j < 64; ++j) {
                const int jg = jj0 + j;
                const float v = acc[j];
                if (EMODE == EP_STORE) {
                    C[(size_t)m * ldc + jg] = v;
                } else if (EMODE == EP_ATT) {
                    s_att += tanhf(v + hWa[(size_t)(m >> 6) * UDIM + jg]) * Va[jg];
                } else if (EMODE == EP_G1) {
                    const float o = v + bias[jg];
                    if (jg < 1024) g_z[(size_t)m * UDIM + jg] = hsig(o + g_G2[(size_t)m * 2048 + jg]);
                    else if (jg < 2048) {
                        const int jj = jg - 1024;
                        const float r = hsig(o + g_G2[(size_t)m * 2048 + jg]);
                        g_rh[(size_t)m * UDIM + jj] = tf32r(r * hraw[(size_t)m * UDIM + jj]);
                    } else g_G1hh[(size_t)m * UDIM + jg - 2048] = o;
                } else {
                    const float hh = tanhf(g_G1hh[(size_t)m * UDIM + jg] + v);
                    const float z  = g_z[(size_t)m * UDIM + jg];
                    outp[(size_t)m * 1088 + 64 + jg] = z * hraw[(size_t)m * UDIM + jg] + (1.f - z) * hh;
                }
            }
        }
    }
    if (EMODE == EP_ATT && tid < 128)
        C[(size_t)m * NBX_ATT + blockIdx.x] = s_att;
#endif
}

// ---------------- softmax over T + context; alpha -> out, c_t -> g_x ----------------
__global__ __launch_bounds__(256)
void attn_kernel(const float* __restrict__ E, float* __restrict__ out)
{
    const int b   = blockIdx.x;
    const int tid = threadIdx.x;
    __shared__ float alpha[TLEN];

    if (tid < TLEN) {
        const float* ep = g_epart + (size_t)(b * TLEN + tid) * NBX_ATT;
        float e = 0.f;
        #pragma unroll
        for (int p = 0; p < NBX_ATT; ++p) e += ep[p];
        alpha[tid] = e;
    }
    __syncthreads();
    if (tid < 32) {
        float v0 = alpha[tid], v1 = alpha[tid + 32];
        float mx = fmaxf(v0, v1);
        #pragma unroll
        for (int off = 16; off > 0; off >>= 1)
            mx = fmaxf(mx, __shfl_xor_sync(0xffffffffu, mx, off));
        float e0 = expf(v0 - mx), e1 = expf(v1 - mx);
        float s = e0 + e1;
        #pragma unroll
        for (int off = 16; off > 0; off >>= 1)
            s += __shfl_xor_sync(0xffffffffu, s, off);
        float inv = 1.f / s;
        alpha[tid]      = e0 * inv;
        alpha[tid + 32] = e1 * inv;
    }
    __syncthreads();
    if (tid < TLEN)
        out[(size_t)b * 1088 + tid] = alpha[tid];

    const float* Eb = E + (size_t)b * TLEN * EDIM;
    float a0 = 0.f, a1 = 0.f, a2 = 0.f, a3 = 0.f;
    for (int t = 0; t < TLEN; ++t) {
        const float w = alpha[t];
        const float* row = Eb + (size_t)t * EDIM;
        a0 = fmaf(w, row[tid +   0], a0);
        a1 = fmaf(w, row[tid + 256], a1);
        a2 = fmaf(w, row[tid + 512], a2);
        a3 = fmaf(w, row[tid + 768], a3);
    }
    float* xr = g_x + (size_t)b * (XDIM + EDIM) + XDIM;
    xr[tid +   0] = tf32r(a0);
    xr[tid + 256] = tf32r(a1);
    xr[tid + 512] = tf32r(a2);
    xr[tid + 768] = tf32r(a3);
}

// ---------------- launch ----------------
extern "C" void kernel_launch(void* const* d_in, const int* in_sizes, int n_in,
                              void* d_out, int out_size)
{
    (void)in_sizes; (void)n_in; (void)out_size;
    const float* inputs = (const float*)d_in[0];
    const float* h      = (const float*)d_in[1];
    const float* E      = (const float*)d_in[2];
    const float* kern   = (const float*)d_in[3];
    const float* rker   = (const float*)d_in[4];
    const float* bias   = (const float*)d_in[5];
    const float* Wa     = (const float*)d_in[6];
    const float* Va     = (const float*)d_in[7];
    float* out = (float*)d_out;

    float *tanhE, *tanhH, *h32, *xbuf, *hWa, *epart, *G2, *rh;
    float *WaTlo, *WaThi, *kernT, *rkerT;
    cudaGetSymbolAddress((void**)&tanhE, g_tanhE);
    cudaGetSymbolAddress((void**)&tanhH, g_tanh_h);
    cudaGetSymbolAddress((void**)&h32,   g_h32);
    cudaGetSymbolAddress((void**)&xbuf,  g_x);
    cudaGetSymbolAddress((void**)&hWa,   g_hWa);
    cudaGetSymbolAddress((void**)&epart, g_epart);
    cudaGetSymbolAddress((void**)&G2,    g_G2);
    cudaGetSymbolAddress((void**)&rh,    g_rh);
    cudaGetSymbolAddress((void**)&WaTlo, g_WaT_lo);
    cudaGetSymbolAddress((void**)&WaThi, g_WaT_hi);
    cudaGetSymbolAddress((void**)&kernT, g_kernT);
    cudaGetSymbolAddress((void**)&rkerT, g_rkerT);

    cudaFuncSetAttribute(tgemm_kernel<EP_STORE>, cudaFuncAttributeMaxDynamicSharedMemorySize, SM_TOTAL);
    cudaFuncSetAttribute(tgemm_kernel<EP_ATT  >, cudaFuncAttributeMaxDynamicSharedMemorySize, SM_TOTAL);
    cudaFuncSetAttribute(tgemm_kernel<EP_G1  >,  cudaFuncAttributeMaxDynamicSharedMemorySize, SM_TOTAL);
    cudaFuncSetAttribute(tgemm_kernel<EP_GRU >,  cudaFuncAttributeMaxDynamicSharedMemorySize, SM_TOTAL);

    // [0] weight transposes (tf32-rounded)
    transpose_all_kernel<<<9728, dim3(32, 8)>>>(Wa, kern, rker);

    // [1] tanh(E), tf32-rounded
    const int n4 = BSZ * TLEN * EDIM / 4;
    tanh4_kernel<<<n4 / 256, 256>>>((const float4*)E, (float4*)tanhE, n4);

    // [2] prep: tf32(h), tf32(tanh h), g_x[:, :512]
    prep_kernel<<<(BSZ * UDIM + 255) / 256, 256>>>(h, inputs);

    // [3] hWa = tanh(h) @ Wa[:U]            M=512  N=1024 K=1024
    tgemm_kernel<EP_STORE><<<dim3(4, 4), 256, SM_TOTAL>>>(
        tanhH, UDIM, WaTlo, UDIM, 32, hWa, UDIM, nullptr, nullptr, nullptr, nullptr, nullptr);

    // [4] G2 = h @ rker[:, :2048]           M=512  N=2048 K=1024  (before G1: EP_G1 reads it)
    tgemm_kernel<EP_STORE><<<dim3(8, 4), 256, SM_TOTAL>>>(
        h32, UDIM, rkerT, UDIM, 32, G2, 2 * UDIM, nullptr, nullptr, nullptr, nullptr, nullptr);

    // [5] attention GEMM + fused e-partials  M=32768 N=1024 K=1024
    tgemm_kernel<EP_ATT><<<dim3(NBX_ATT, 256), 256, SM_TOTAL>>>(
        tanhE, EDIM, WaThi, UDIM, 32, epart, 0, hWa, Va, nullptr, nullptr, nullptr);

    // [6] softmax + alpha -> out, c_t -> g_x
    attn_kernel<<<BSZ, 256>>>(E, out);

    // [7] G1 = x @ kern + bias, fused z/r gates  M=512 N=3072 K=1536
    tgemm_kernel<EP_G1><<<dim3(12, 4), 256, SM_TOTAL>>>(
        xbuf, XDIM + EDIM, kernT, XDIM + EDIM, 48, nullptr, 0, nullptr, nullptr, bias, h, nullptr);

    // [8] Ghh = (r*h) @ rker[:, 2048:], fused h_new -> out   M=512 N=1024 K=1024
    tgemm_kernel<EP_GRU><<<dim3(4, 4), 256, SM_TOTAL>>>(
        rh, UDIM, rkerT + (size_t)2048 * UDIM, UDIM, 32, nullptr, 0, nullptr, nullptr, nullptr, h, out);
}

// round 15
// speedup vs baseline: 1.4745x; 1.4745x over previous
#include <cuda_runtime.h>
#include <math.h>
#include <stdint.h>

#define BSZ  512
#define TLEN 64
#define XDIM 512
#define EDIM 1024
#define UDIM 1024
#define NBX_ATT 4

#define TM 128
#define TN 256
#define TKB 64          // K elements per sync round (2 x 32-k half-tiles)
#define NSTAGE 2

#if defined(__CUDA_ARCH_FEAT_SM103_ALL) || defined(__CUDA_ARCH_FEAT_SM100_ALL) || defined(__CUDA_ARCH_FEAT_SM101_ALL)
#define HAS_TCGEN05 1
#else
#define HAS_TCGEN05 0
#endif

// ---------------- static scratch ----------------
__device__ float g_tanhE [(size_t)BSZ * TLEN * EDIM];   // tf32 tanh(E)
__device__ float g_tanh_h[(size_t)BSZ * UDIM];          // tf32 tanh(h)
__device__ float g_h32   [(size_t)BSZ * UDIM];          // tf32 h
__device__ float g_x     [(size_t)BSZ * (XDIM + EDIM)]; // tf32 [inputs | c_t]
__device__ float g_hWa   [(size_t)BSZ * UDIM];
__device__ float g_epart [(size_t)BSZ * TLEN * NBX_ATT];
__device__ float g_G1    [(size_t)BSZ * 3 * UDIM];
__device__ float g_G2    [(size_t)BSZ * 2 * UDIM];
__device__ float g_z     [(size_t)BSZ * UDIM];
__device__ float g_rh    [(size_t)BSZ * UDIM];          // tf32(r*h)
__device__ float g_Ghh   [(size_t)BSZ * UDIM];
// K-major transposed, tf32-rounded weights: W_T[n][k]
__device__ float g_WaT_lo[(size_t)UDIM * UDIM];
__device__ float g_WaT_hi[(size_t)UDIM * UDIM];
__device__ float g_kernT [(size_t)3 * UDIM * (XDIM + EDIM)];
__device__ float g_rkerT [(size_t)3 * UDIM * UDIM];

__device__ __forceinline__ uint32_t f2tf32(float f) {
    uint32_t r;
    asm("cvt.rna.tf32.f32 %0, %1;" : "=r"(r) : "f"(f));
    return r;
}
__device__ __forceinline__ float tf32r(float f) { return __uint_as_float(f2tf32(f)); }

// ---------------- PTX helpers (sm_103a branch only) ----------------
#if HAS_TCGEN05
__device__ __forceinline__ uint32_t smem_u32(const void* p) {
    uint32_t a;
    asm("{ .reg .u64 t; cvta.to.shared.u64 t, %1; cvt.u32.u64 %0, t; }" : "=r"(a) : "l"(p));
    return a;
}
#define SW128(x) ((x) ^ (((x) >> 3) & 0x70))
#define TCG_ALLOC(sm, n)  asm volatile("tcgen05.alloc.cta_group::1.sync.aligned.shared::cta.b32 [%0], %1;" :: "r"(sm), "r"(n) : "memory")
#define TCG_DEALLOC(t, n) asm volatile("tcgen05.dealloc.cta_group::1.sync.aligned.b32 %0, %1;" :: "r"(t), "r"(n))
#define TCG_RELINQ()      asm volatile("tcgen05.relinquish_alloc_permit.cta_group::1.sync.aligned;")
#define TCG_COMMIT(mb)    asm volatile("tcgen05.commit.cta_group::1.mbarrier::arrive::one.shared::cluster.b64 [%0];" :: "r"(mb) : "memory")
#define TCG_FENCE_AFTER() asm volatile("tcgen05.fence::after_thread_sync;" ::: "memory")
#define TCG_FENCE_BEFORE() asm volatile("tcgen05.fence::before_thread_sync;" ::: "memory")
#define TCG_WAIT_LD()     asm volatile("tcgen05.wait::ld.sync.aligned;" ::: "memory")
#define FENCE_ASYNC()     asm volatile("fence.proxy.async.shared::cta;" ::: "memory")
#define MBAR_INIT(mb, c)  asm volatile("mbarrier.init.shared.b64 [%0], %1;" :: "r"(mb), "r"(c) : "memory")
#define CP_ASYNC16(dst, src) asm volatile("cp.async.cg.shared.global [%0], [%1], 16;" :: "r"(dst), "l"(src) : "memory")
#define CP_COMMIT()       asm volatile("cp.async.commit_group;" ::: "memory")

__device__ __forceinline__ void mbar_wait(uint32_t mb, uint32_t parity) {
    uint32_t done;
    asm volatile("{\n\t.reg .pred p;\n\t"
        "mbarrier.try_wait.parity.acquire.cta.shared::cta.b64 p, [%1], %2;\n\t"
        "selp.b32 %0, 1, 0, p;\n\t}"
        : "=r"(done) : "r"(mb), "r"(parity) : "memory");
    if (!done) {
        asm volatile("{\n\t.reg .pred P1;\n\t"
            "W_%=:\n\t"
            "mbarrier.try_wait.parity.acquire.cta.shared::cta.b64 P1, [%0], %1, 0x989680;\n\t"
            "@P1 bra.uni D_%=;\n\t"
            "bra.uni W_%=;\n\t"
            "D_%=:\n\t}"
            :: "r"(mb), "r"(parity) : "memory");
    }
}
__device__ __forceinline__ void mma_tf32_ss(uint32_t d, uint64_t ad, uint64_t bd,
                                            uint32_t idesc, uint32_t acc) {
    asm volatile("{\n\t.reg .pred p;\n\t"
        "setp.ne.u32 p, %5, 0;\n\t"
        "tcgen05.mma.cta_group::1.kind::tf32 [%0], %1, %2, %3, {%4, %4, %4, %4}, p;\n\t}"
        :: "r"(d), "l"(ad), "l"(bd), "r"(idesc), "r"(0u), "r"(acc) : "memory");
}
__device__ __forceinline__ void tmem_ld32(uint32_t* r, uint32_t a) {
    asm volatile("tcgen05.ld.sync.aligned.32x32b.x32.b32 "
        "{%0,%1,%2,%3,%4,%5,%6,%7,%8,%9,%10,%11,%12,%13,%14,%15,"
        "%16,%17,%18,%19,%20,%21,%22,%23,%24,%25,%26,%27,%28,%29,%30,%31}, [%32];"
        : "=r"(r[0]),"=r"(r[1]),"=r"(r[2]),"=r"(r[3]),"=r"(r[4]),"=r"(r[5]),"=r"(r[6]),"=r"(r[7]),
          "=r"(r[8]),"=r"(r[9]),"=r"(r[10]),"=r"(r[11]),"=r"(r[12]),"=r"(r[13]),"=r"(r[14]),"=r"(r[15]),
          "=r"(r[16]),"=r"(r[17]),"=r"(r[18]),"=r"(r[19]),"=r"(r[20]),"=r"(r[21]),"=r"(r[22]),"=r"(r[23]),
          "=r"(r[24]),"=r"(r[25]),"=r"(r[26]),"=r"(r[27]),"=r"(r[28]),"=r"(r[29]),"=r"(r[30]),"=r"(r[31])
        : "r"(a));
}
__device__ __forceinline__ uint64_t mk_desc(uint32_t addr) {
    const uint64_t base = (uint64_t(2) << 61) | (uint64_t(1) << 46)
                        | (uint64_t(64) << 32) | (uint64_t(1) << 16);
    return base | ((uint64_t)(addr >> 4) & 0x3FFF);
}
#endif // HAS_TCGEN05

// ---------------- tanh(E), tf32-rounded ----------------
__global__ void tanh4_kernel(const float4* __restrict__ in, float4* __restrict__ out, int n4)
{
    int i = blockIdx.x * blockDim.x + threadIdx.x;
    if (i < n4) {
        float4 v = in[i];
        uint4 u = make_uint4(f2tf32(tanhf(v.x)), f2tf32(tanhf(v.y)),
                             f2tf32(tanhf(v.z)), f2tf32(tanhf(v.w)));
        *reinterpret_cast<uint4*>(&out[i]) = u;
    }
}

// ---------------- prep: tf32(h), tf32(tanh h), g_x[:, :512] ----------------
__global__ void prep_kernel(const float* __restrict__ h, const float* __restrict__ inputs)
{
    const int idx = blockIdx.x * blockDim.x + threadIdx.x;
    if (idx < BSZ * UDIM) {
        float v = h[idx];
        g_h32[idx]    = tf32r(v);
        g_tanh_h[idx] = tf32r(tanhf(v));
    }
    if (idx < BSZ * XDIM) {
        const int m = idx >> 9, j = idx & 511;
        g_x[(size_t)m * (XDIM + EDIM) + j] = tf32r(inputs[idx]);
    }
}

// ---------------- fused weight transposes, tf32-rounded ----------------
__global__ __launch_bounds__(256)
void transpose_all_kernel(const float* __restrict__ Wa, const float* __restrict__ kern,
                          const float* __restrict__ rker)
{
    const int bid = blockIdx.x;
    const float* src; float* dst; int ld, K, nb, kb;
    if (bid < 1024)      { src = Wa;                     dst = g_WaT_lo; ld = 1024; K = 1024; nb = bid & 31;  kb = bid >> 5; }
    else if (bid < 2048) { int b = bid - 1024; src = Wa + 1024 * 1024; dst = g_WaT_hi; ld = 1024; K = 1024; nb = b & 31; kb = b >> 5; }
    else if (bid < 6656) { int b = bid - 2048; src = kern; dst = g_kernT; ld = 3072; K = 1536; nb = b % 96; kb = b / 96; }
    else                 { int b = bid - 6656; src = rker; dst = g_rkerT; ld = 3072; K = 1024; nb = b % 96; kb = b / 96; }

    __shared__ float t[32][33];
    const int tx = threadIdx.x, ty = threadIdx.y;
    const int n0 = nb * 32, k0 = kb * 32;
    #pragma unroll
    for (int i = 0; i < 32; i += 8)
        t[ty + i][tx] = src[(size_t)(k0 + ty + i) * ld + n0 + tx];
    __syncthreads();
    #pragma unroll
    for (int i = 0; i < 32; i += 8)
        dst[(size_t)(n0 + ty + i) * K + k0 + tx] = tf32r(t[tx][ty + i]);
}

// ---------------- GEMM: 128x256 tile, TK=64 per sync round, 2-stage cp.async ----------------
enum { EP_STORE = 0, EP_BIAS = 1, EP_ATT = 2 };

// stage layout: [A_h0 16K][A_h1 16K][B_h0 32K][B_h1 32K] = 96KB
#define SM_STAGE_BYTES 98304
#define SM_CTRL (NSTAGE * SM_STAGE_BYTES)      // 196608
#define SM_TOTAL (SM_CTRL + 64)

template<int EMODE>
__global__ __launch_bounds__(256)
void tgemm_kernel(const float* __restrict__ A, int lda,
                  const float* __restrict__ Bt, int ldb, int nK,
                  float* __restrict__ C, int ldc,
                  const float* __restrict__ hWa, const float* __restrict__ Va,
                  const float* __restrict__ bias)
{
    extern __shared__ char smc[];
    const int tid = threadIdx.x;
    const int row0 = blockIdx.y * TM;
    const int col0 = blockIdx.x * TN;

#if HAS_TCGEN05
    const uint32_t sb  = smem_u32(smc);
    const int wid = tid >> 5;
    const int lid = tid & 31;

    if (wid == 0) { TCG_ALLOC(sb + SM_CTRL, TN); TCG_RELINQ(); }
    if (tid == 0) {
        #pragma unroll
        for (int s = 0; s < NSTAGE; ++s) MBAR_INIT(sb + SM_CTRL + 8 + 8 * s, 1);
    }
    __syncthreads();
    uint32_t tmem;
    asm volatile("ld.shared.b32 %0, [%1];" : "=r"(tmem) : "r"(sb + SM_CTRL));

    const uint32_t idesc = (1u << 4) | (2u << 7) | (2u << 10)
                         | ((TN / 8) << 17) | ((TM / 16) << 24);

    // per-thread cp.async slots for a 64-k chunk:
    // A: 128 rows x 256B = 2048 x16B -> 8/thread; B: 256 rows x 256B = 4096 x16B -> 16/thread
    // element (r, kq) kq=0..15: half = kq>>3, qq = kq&7
    int arr[8], akq[8], brr[16], bkq[16];
    #pragma unroll
    for (int i = 0; i < 8; ++i)  { const int s = i * 256 + tid; arr[i] = s >> 4; akq[i] = s & 15; }
    #pragma unroll
    for (int i = 0; i < 16; ++i) { const int s = i * 256 + tid; brr[i] = s >> 4; bkq[i] = s & 15; }

    uint32_t phbits = 0;
    const int itMax = nK + NSTAGE - 1;
    for (int it = 0; it < itMax; ++it) {
        if (it < nK) {
            const int s = it & (NSTAGE - 1);
            if (it >= NSTAGE) {
                mbar_wait(sb + SM_CTRL + 8 + 8 * s, (phbits >> s) & 1u);
                phbits ^= 1u << s;
            }
            const int k0 = it * TKB;
            const uint32_t sA = sb + s * SM_STAGE_BYTES;
            const uint32_t sB = sA + 32768;
            #pragma unroll
            for (int i = 0; i < 8; ++i) {
                const int kq = akq[i];
                CP_ASYNC16(sA + (kq >> 3) * 16384 + SW128(arr[i] * 128 + (kq & 7) * 16),
                           &A[(size_t)(row0 + arr[i]) * lda + k0 + kq * 4]);
            }
            #pragma unroll
            for (int i = 0; i < 16; ++i) {
                const int kq = bkq[i];
                CP_ASYNC16(sB + (kq >> 3) * 32768 + SW128(brr[i] * 128 + (kq & 7) * 16),
                           &Bt[(size_t)(col0 + brr[i]) * ldb + k0 + kq * 4]);
            }
        }
        CP_COMMIT();
        const int j = it - (NSTAGE - 1);
        if (j >= 0) {
            asm volatile("cp.async.wait_group %0;" :: "n"(NSTAGE - 1) : "memory");
            __syncthreads();
            if (tid == 0) {
                FENCE_ASYNC();
                const int s = j & (NSTAGE - 1);
                const uint32_t sA = sb + s * SM_STAGE_BYTES;
                #pragma unroll
                for (int half = 0; half < 2; ++half) {
                    const uint64_t ad = mk_desc(sA + half * 16384);
                    const uint64_t bd = mk_desc(sA + 32768 + half * 32768);
                    #pragma unroll
                    for (int ss = 0; ss < 4; ++ss)
                        mma_tf32_ss(tmem, ad + ss * 2, bd + ss * 2, idesc,
                                    (j > 0 || half > 0 || ss > 0) ? 1u : 0u);
                }
                TCG_COMMIT(sb + SM_CTRL + 8 + 8 * s);
            }
        }
    }
    {
        const int sl = (nK - 1) & (NSTAGE - 1);
        mbar_wait(sb + SM_CTRL + 8 + 8 * sl, (phbits >> sl) & 1u);
    }
    TCG_FENCE_AFTER();

    // ---- epilogue: 8 warps, two column halves (R10 exact) ----
    const int sp = wid & 3;
    const int hf = wid >> 2;
    const int m  = row0 + sp * 32 + lid;

    if (EMODE == EP_ATT) {
        const int b = m >> 6;
        const float* hrow = hWa + (size_t)b * UDIM;
        float s = 0.f;
        #pragma unroll
        for (int c = 0; c < 4; ++c) {
            const int cc = hf * 4 + c;
            uint32_t regs[32];
            tmem_ld32(regs, tmem + cc * 32);
            TCG_WAIT_LD();
            const int jj0 = col0 + cc * 32;
            #pragma unroll
            for (int j2 = 0; j2 < 32; ++j2)
                s += tanhf(__uint_as_float(regs[j2]) + hrow[jj0 + j2]) * Va[jj0 + j2];
        }
        float* sm = reinterpret_cast<float*>(smc);
        __syncthreads();
        sm[wid * 32 + lid] = s;
        __syncthreads();
        if (wid < 4)
            C[(size_t)m * NBX_ATT + blockIdx.x] = sm[wid * 32 + lid] + sm[(wid + 4) * 32 + lid];
    } else {
        #pragma unroll
        for (int c = 0; c < 4; ++c) {
            const int cc = hf * 4 + c;
            uint32_t regs[32];
            tmem_ld32(regs, tmem + cc * 32);
            TCG_WAIT_LD();
            const int jj0 = col0 + cc * 32;
            #pragma unroll
            for (int j2 = 0; j2 < 32; j2 += 4) {
                float4 o;
                o.x = __uint_as_float(regs[j2 + 0]);
                o.y = __uint_as_float(regs[j2 + 1]);
                o.z = __uint_as_float(regs[j2 + 2]);
                o.w = __uint_as_float(regs[j2 + 3]);
                if (EMODE == EP_BIAS) {
                    o.x += bias[jj0 + j2 + 0]; o.y += bias[jj0 + j2 + 1];
                    o.z += bias[jj0 + j2 + 2]; o.w += bias[jj0 + j2 + 3];
                }
                *reinterpret_cast<float4*>(&C[(size_t)m * ldc + jj0 + j2]) = o;
            }
        }
    }
    TCG_FENCE_BEFORE();
    __syncthreads();
    if (wid == 0) TCG_DEALLOC(tmem, TN);

#else
    // ============ FFMA fallback (plain-sm_103 pass; dead code on GB300) ============
    float* Bs = reinterpret_cast<float*>(smc);
    const int Ktot = nK * TKB;
    const int m = row0 + (tid & 127);
    float s_att = 0.f;

    for (int nc = 0; nc < 4; ++nc) {
        float acc[64];
        #pragma unroll
        for (int j = 0; j < 64; ++j) acc[j] = 0.f;
        for (int kt = 0; kt < Ktot; kt += 32) {
            for (int i = tid; i < 32 * 64; i += 256) {
                const int kk = i & 31, j = i >> 5;
                Bs[kk * 64 + j] = Bt[(size_t)(col0 + nc * 64 + j) * ldb + kt + kk];
            }
            __syncthreads();
            if (tid < 128) {
                float av[32];
                #pragma unroll
                for (int q = 0; q < 32; q += 4) {
                    float4 v = *reinterpret_cast<const float4*>(&A[(size_t)m * lda + kt + q]);
                    av[q] = v.x; av[q + 1] = v.y; av[q + 2] = v.z; av[q + 3] = v.w;
                }
                #pragma unroll 4
                for (int kk = 0; kk < 32; ++kk) {
                    const float a = av[kk];
                    #pragma unroll
                    for (int j = 0; j < 64; ++j)
                        acc[j] = fmaf(a, Bs[kk * 64 + j], acc[j]);
                }
            }
            __syncthreads();
        }
        if (tid < 128) {
            const int jj0 = col0 + nc * 64;
            if (EMODE == EP_ATT) {
                const int b = m >> 6;
                for (int j = 0; j < 64; ++j)
                    s_att += tanhf(acc[j] + hWa[(size_t)b * UDIM + jj0 + j]) * Va[jj0 + j];
            } else {
                for (int j = 0; j < 64; ++j) {
                    float o = acc[j];
                    if (EMODE == EP_BIAS) o += bias[jj0 + j];
                    C[(size_t)m * ldc + jj0 + j] = o;
                }
            }
        }
    }
    if (EMODE == EP_ATT && tid < 128)
        C[(size_t)m * NBX_ATT + blockIdx.x] = s_att;
#endif
}

// ---------------- softmax over T + context; alpha -> out, c_t -> g_x ----------------
__global__ __launch_bounds__(256)
void attn_kernel(const float* __restrict__ E, float* __restrict__ out)
{
    const int b   = blockIdx.x;
    const int tid = threadIdx.x;
    __shared__ float alpha[TLEN];

    if (tid < TLEN) {
        const float* ep = g_epart + (size_t)(b * TLEN + tid) * NBX_ATT;
        float e = 0.f;
        #pragma unroll
        for (int p = 0; p < NBX_ATT; ++p) e += ep[p];
        alpha[tid] = e;
    }
    __syncthreads();
    if (tid < 32) {
        float v0 = alpha[tid], v1 = alpha[tid + 32];
        float mx = fmaxf(v0, v1);
        #pragma unroll
        for (int off = 16; off > 0; off >>= 1)
            mx = fmaxf(mx, __shfl_xor_sync(0xffffffffu, mx, off));
        float e0 = expf(v0 - mx), e1 = expf(v1 - mx);
        float s = e0 + e1;
        #pragma unroll
        for (int off = 16; off > 0; off >>= 1)
            s += __shfl_xor_sync(0xffffffffu, s, off);
        float inv = 1.f / s;
        alpha[tid]      = e0 * inv;
        alpha[tid + 32] = e1 * inv;
    }
    __syncthreads();
    if (tid < TLEN)
        out[(size_t)b * 1088 + tid] = alpha[tid];

    const float* Eb = E + (size_t)b * TLEN * EDIM;
    float a0 = 0.f, a1 = 0.f, a2 = 0.f, a3 = 0.f;
    for (int t = 0; t < TLEN; ++t) {
        const float w = alpha[t];
        const float* row = Eb + (size_t)t * EDIM;
        a0 = fmaf(w, row[tid +   0], a0);
        a1 = fmaf(w, row[tid + 256], a1);
        a2 = fmaf(w, row[tid + 512], a2);
        a3 = fmaf(w, row[tid + 768], a3);
    }
    float* xr = g_x + (size_t)b * (XDIM + EDIM) + XDIM;
    xr[tid +   0] = tf32r(a0);
    xr[tid + 256] = tf32r(a1);
    xr[tid + 512] = tf32r(a2);
    xr[tid + 768] = tf32r(a3);
}

// ---------------- gates: z, r; store z and tf32(r*h) (R10 exact) ----------------
__global__ __launch_bounds__(256)
void gates_kernel(const float* __restrict__ h)
{
    const int idx = blockIdx.x * blockDim.x + threadIdx.x;
    if (idx >= BSZ * UDIM) return;
    const int m = idx >> 10;
    const int j = idx & 1023;
    const float* G1 = g_G1 + (size_t)m * 3 * UDIM;
    const float* G2 = g_G2 + (size_t)m * 2 * UDIM;
    float z = fminf(fmaxf(0.2f * (G1[j]        + G2[j])        + 0.5f, 0.f), 1.f);
    float r = fminf(fmaxf(0.2f * (G1[j + 1024] + G2[j + 1024]) + 0.5f, 0.f), 1.f);
    g_z[idx]  = z;
    g_rh[idx] = tf32r(r * h[idx]);
}

// ---------------- final: h_new -> out (R10 exact) ----------------
__global__ __launch_bounds__(256)
void gru_final_kernel(const float* __restrict__ h, float* __restrict__ out)
{
    const int idx = blockIdx.x * blockDim.x + threadIdx.x;
    if (idx >= BSZ * UDIM) return;
    const int m = idx >> 10;
    const int j = idx & 1023;
    float hh = tanhf(g_G1[(size_t)m * 3 * UDIM + 2048 + j] + g_Ghh[idx]);
    float z  = g_z[idx];
    out[(size_t)m * 1088 + 64 + j] = z * h[idx] + (1.f - z) * hh;
}

// ---------------- launch (R10 structure; nK now in 64-k units) ----------------
extern "C" void kernel_launch(void* const* d_in, const int* in_sizes, int n_in,
                              void* d_out, int out_size)
{
    (void)in_sizes; (void)n_in; (void)out_size;
    const float* inputs = (const float*)d_in[0];
    const float* h      = (const float*)d_in[1];
    const float* E      = (const float*)d_in[2];
    const float* kern   = (const float*)d_in[3];
    const float* rker   = (const float*)d_in[4];
    const float* bias   = (const float*)d_in[5];
    const float* Wa     = (const float*)d_in[6];
    const float* Va     = (const float*)d_in[7];
    float* out = (float*)d_out;

    float *tanhE, *tanhH, *h32, *xbuf, *hWa, *epart, *G1, *G2, *rh, *Ghh;
    float *WaTlo, *WaThi, *kernT, *rkerT;
    cudaGetSymbolAddress((void**)&tanhE, g_tanhE);
    cudaGetSymbolAddress((void**)&tanhH, g_tanh_h);
    cudaGetSymbolAddress((void**)&h32,   g_h32);
    cudaGetSymbolAddress((void**)&xbuf,  g_x);
    cudaGetSymbolAddress((void**)&hWa,   g_hWa);
    cudaGetSymbolAddress((void**)&epart, g_epart);
    cudaGetSymbolAddress((void**)&G1,    g_G1);
    cudaGetSymbolAddress((void**)&G2,    g_G2);
    cudaGetSymbolAddress((void**)&rh,    g_rh);
    cudaGetSymbolAddress((void**)&Ghh,   g_Ghh);
    cudaGetSymbolAddress((void**)&WaTlo, g_WaT_lo);
    cudaGetSymbolAddress((void**)&WaThi, g_WaT_hi);
    cudaGetSymbolAddress((void**)&kernT, g_kernT);
    cudaGetSymbolAddress((void**)&rkerT, g_rkerT);

    cudaFuncSetAttribute(tgemm_kernel<EP_STORE>, cudaFuncAttributeMaxDynamicSharedMemorySize, SM_TOTAL);
    cudaFuncSetAttribute(tgemm_kernel<EP_ATT  >, cudaFuncAttributeMaxDynamicSharedMemorySize, SM_TOTAL);
    cudaFuncSetAttribute(tgemm_kernel<EP_BIAS >, cudaFuncAttributeMaxDynamicSharedMemorySize, SM_TOTAL);

    // [0] weight transposes (tf32-rounded)
    transpose_all_kernel<<<9728, dim3(32, 8)>>>(Wa, kern, rker);

    // [1] tanh(E), tf32-rounded
    const int n4 = BSZ * TLEN * EDIM / 4;
    tanh4_kernel<<<n4 / 256, 256>>>((const float4*)E, (float4*)tanhE, n4);

    // [2] prep: tf32(h), tf32(tanh h), g_x[:, :512]
    prep_kernel<<<(BSZ * UDIM + 255) / 256, 256>>>(h, inputs);

    // [3] hWa = tanh(h) @ Wa[:U]            M=512  N=1024 K=1024 (nK=16)
    tgemm_kernel<EP_STORE><<<dim3(4, 4), 256, SM_TOTAL>>>(
        tanhH, UDIM, WaTlo, UDIM, 16, hWa, UDIM, nullptr, nullptr, nullptr);

    // [4] attention GEMM + fused e-partials  M=32768 N=1024 K=1024 (nK=16)
    tgemm_kernel<EP_ATT><<<dim3(NBX_ATT, 256), 256, SM_TOTAL>>>(
        tanhE, EDIM, WaThi, UDIM, 16, epart, 0, hWa, Va, nullptr);

    // [5] softmax + alpha -> out, c_t -> g_x
    attn_kernel<<<BSZ, 256>>>(E, out);

    // [6] G1 = x @ kern + bias               M=512  N=3072 K=1536 (nK=24)
    tgemm_kernel<EP_BIAS><<<dim3(12, 4), 256, SM_TOTAL>>>(
        xbuf, XDIM + EDIM, kernT, XDIM + EDIM, 24, G1, 3 * UDIM, nullptr, nullptr, bias);

    // [7] G2 = h @ rker[:, :2048]            M=512  N=2048 K=1024 (nK=16)
    tgemm_kernel<EP_STORE><<<dim3(8, 4), 256, SM_TOTAL>>>(
        h32, UDIM, rkerT, UDIM, 16, G2, 2 * UDIM, nullptr, nullptr, nullptr);

    // [8] gates
    gates_kernel<<<(BSZ * UDIM + 255) / 256, 256>>>(h);

    // [9] Ghh = (r*h) @ rker[:, 2048:]       M=512  N=1024 K=1024 (nK=16)
    tgemm_kernel<EP_STORE><<<dim3(4, 4), 256, SM_TOTAL>>>(
        rh, UDIM, rkerT + (size_t)2048 * UDIM, UDIM, 16, Ghh, UDIM, nullptr, nullptr, nullptr);

    // [10] h_new
    gru_final_kernel<<<(BSZ * UDIM + 255) / 256, 256>>>(h, out);
}

// round 16
// speedup vs baseline: 1.5271x; 1.0357x over previous
#include <cuda_runtime.h>
#include <math.h>
#include <stdint.h>

#define BSZ  512
#define TLEN 64
#define XDIM 512
#define EDIM 1024
#define UDIM 1024
#define NBX_ATT 4

#define TM 128
#define TN 256

#if defined(__CUDA_ARCH_FEAT_SM103_ALL) || defined(__CUDA_ARCH_FEAT_SM100_ALL) || defined(__CUDA_ARCH_FEAT_SM101_ALL)
#define HAS_TCGEN05 1
#else
#define HAS_TCGEN05 0
#endif

// ---------------- static scratch ----------------
__device__ float g_tanhE [(size_t)BSZ * TLEN * EDIM];   // tf32 tanh(E)
__device__ float g_tanh_h[(size_t)BSZ * UDIM];          // tf32 tanh(h)
__device__ float g_h32   [(size_t)BSZ * UDIM];          // tf32 h
__device__ float g_x     [(size_t)BSZ * (XDIM + EDIM)]; // tf32 [inputs | c_t]
__device__ float g_hWa   [(size_t)BSZ * UDIM];
__device__ float g_epart [(size_t)BSZ * TLEN * NBX_ATT];
__device__ float g_G1    [(size_t)BSZ * 3 * UDIM];
__device__ float g_G2    [(size_t)BSZ * 2 * UDIM];
__device__ float g_z     [(size_t)BSZ * UDIM];
__device__ float g_rh    [(size_t)BSZ * UDIM];          // tf32(r*h)
__device__ float g_Ghh   [(size_t)BSZ * UDIM];
// K-major transposed, tf32-rounded weights: W_T[n][k]
__device__ float g_WaT_lo[(size_t)UDIM * UDIM];
__device__ float g_WaT_hi[(size_t)UDIM * UDIM];
__device__ float g_kernT [(size_t)3 * UDIM * (XDIM + EDIM)];
__device__ float g_rkerT [(size_t)3 * UDIM * UDIM];

__device__ __forceinline__ uint32_t f2tf32(float f) {
    uint32_t r;
    asm("cvt.rna.tf32.f32 %0, %1;" : "=r"(r) : "f"(f));
    return r;
}
__device__ __forceinline__ float tf32r(float f) { return __uint_as_float(f2tf32(f)); }

// ---------------- PTX helpers (sm_103a branch only) ----------------
#if HAS_TCGEN05
__device__ __forceinline__ uint32_t smem_u32(const void* p) {
    uint32_t a;
    asm("{ .reg .u64 t; cvta.to.shared.u64 t, %1; cvt.u32.u64 %0, t; }" : "=r"(a) : "l"(p));
    return a;
}
#define SW128(x) ((x) ^ (((x) >> 3) & 0x70))
#define TCG_ALLOC(sm, n)  asm volatile("tcgen05.alloc.cta_group::1.sync.aligned.shared::cta.b32 [%0], %1;" :: "r"(sm), "r"(n) : "memory")
#define TCG_DEALLOC(t, n) asm volatile("tcgen05.dealloc.cta_group::1.sync.aligned.b32 %0, %1;" :: "r"(t), "r"(n))
#define TCG_RELINQ()      asm volatile("tcgen05.relinquish_alloc_permit.cta_group::1.sync.aligned;")
#define TCG_COMMIT(mb)    asm volatile("tcgen05.commit.cta_group::1.mbarrier::arrive::one.shared::cluster.b64 [%0];" :: "r"(mb) : "memory")
#define TCG_FENCE_AFTER() asm volatile("tcgen05.fence::after_thread_sync;" ::: "memory")
#define TCG_FENCE_BEFORE() asm volatile("tcgen05.fence::before_thread_sync;" ::: "memory")
#define TCG_WAIT_LD()     asm volatile("tcgen05.wait::ld.sync.aligned;" ::: "memory")
#define FENCE_ASYNC()     asm volatile("fence.proxy.async.shared::cta;" ::: "memory")
#define MBAR_INIT(mb, c)  asm volatile("mbarrier.init.shared.b64 [%0], %1;" :: "r"(mb), "r"(c) : "memory")
#define CP_ASYNC16(dst, src) asm volatile("cp.async.cg.shared.global [%0], [%1], 16;" :: "r"(dst), "l"(src) : "memory")
#define CP_COMMIT()       asm volatile("cp.async.commit_group;" ::: "memory")

__device__ __forceinline__ void mbar_wait(uint32_t mb, uint32_t parity) {
    uint32_t done;
    asm volatile("{\n\t.reg .pred p;\n\t"
        "mbarrier.try_wait.parity.acquire.cta.shared::cta.b64 p, [%1], %2;\n\t"
        "selp.b32 %0, 1, 0, p;\n\t}"
        : "=r"(done) : "r"(mb), "r"(parity) : "memory");
    if (!done) {
        asm volatile("{\n\t.reg .pred P1;\n\t"
            "W_%=:\n\t"
            "mbarrier.try_wait.parity.acquire.cta.shared::cta.b64 P1, [%0], %1, 0x989680;\n\t"
            "@P1 bra.uni D_%=;\n\t"
            "bra.uni W_%=;\n\t"
            "D_%=:\n\t}"
            :: "r"(mb), "r"(parity) : "memory");
    }
}
__device__ __forceinline__ void mma_tf32_ss(uint32_t d, uint64_t ad, uint64_t bd,
                                            uint32_t idesc, uint32_t acc) {
    asm volatile("{\n\t.reg .pred p;\n\t"
        "setp.ne.u32 p, %5, 0;\n\t"
        "tcgen05.mma.cta_group::1.kind::tf32 [%0], %1, %2, %3, {%4, %4, %4, %4}, p;\n\t}"
        :: "r"(d), "l"(ad), "l"(bd), "r"(idesc), "r"(0u), "r"(acc) : "memory");
}
__device__ __forceinline__ void tmem_ld32(uint32_t* r, uint32_t a) {
    asm volatile("tcgen05.ld.sync.aligned.32x32b.x32.b32 "
        "{%0,%1,%2,%3,%4,%5,%6,%7,%8,%9,%10,%11,%12,%13,%14,%15,"
        "%16,%17,%18,%19,%20,%21,%22,%23,%24,%25,%26,%27,%28,%29,%30,%31}, [%32];"
        : "=r"(r[0]),"=r"(r[1]),"=r"(r[2]),"=r"(r[3]),"=r"(r[4]),"=r"(r[5]),"=r"(r[6]),"=r"(r[7]),
          "=r"(r[8]),"=r"(r[9]),"=r"(r[10]),"=r"(r[11]),"=r"(r[12]),"=r"(r[13]),"=r"(r[14]),"=r"(r[15]),
          "=r"(r[16]),"=r"(r[17]),"=r"(r[18]),"=r"(r[19]),"=r"(r[20]),"=r"(r[21]),"=r"(r[22]),"=r"(r[23]),
          "=r"(r[24]),"=r"(r[25]),"=r"(r[26]),"=r"(r[27]),"=r"(r[28]),"=r"(r[29]),"=r"(r[30]),"=r"(r[31])
        : "r"(a));
}
__device__ __forceinline__ uint64_t mk_desc(uint32_t addr) {
    const uint64_t base = (uint64_t(2) << 61) | (uint64_t(1) << 46)
                        | (uint64_t(64) << 32) | (uint64_t(1) << 16);
    return base | ((uint64_t)(addr >> 4) & 0x3FFF);
}
#endif // HAS_TCGEN05

// ---------------- tanh(E), tf32-rounded ----------------
__global__ void tanh4_kernel(const float4* __restrict__ in, float4* __restrict__ out, int n4)
{
    int i = blockIdx.x * blockDim.x + threadIdx.x;
    if (i < n4) {
        float4 v = in[i];
        uint4 u = make_uint4(f2tf32(tanhf(v.x)), f2tf32(tanhf(v.y)),
                             f2tf32(tanhf(v.z)), f2tf32(tanhf(v.w)));
        *reinterpret_cast<uint4*>(&out[i]) = u;
    }
}

// ---------------- prep: tf32(h), tf32(tanh h), g_x[:, :512] ----------------
__global__ void prep_kernel(const float* __restrict__ h, const float* __restrict__ inputs)
{
    const int idx = blockIdx.x * blockDim.x + threadIdx.x;
    if (idx < BSZ * UDIM) {
        float v = h[idx];
        g_h32[idx]    = tf32r(v);
        g_tanh_h[idx] = tf32r(tanhf(v));
    }
    if (idx < BSZ * XDIM) {
        const int m = idx >> 9, j = idx & 511;
        g_x[(size_t)m * (XDIM + EDIM) + j] = tf32r(inputs[idx]);
    }
}

// ---------------- fused weight transposes, tf32-rounded ----------------
__global__ __launch_bounds__(256)
void transpose_all_kernel(const float* __restrict__ Wa, const float* __restrict__ kern,
                          const float* __restrict__ rker)
{
    const int bid = blockIdx.x;
    const float* src; float* dst; int ld, K, nb, kb;
    if (bid < 1024)      { src = Wa;                     dst = g_WaT_lo; ld = 1024; K = 1024; nb = bid & 31;  kb = bid >> 5; }
    else if (bid < 2048) { int b = bid - 1024; src = Wa + 1024 * 1024; dst = g_WaT_hi; ld = 1024; K = 1024; nb = b & 31; kb = b >> 5; }
    else if (bid < 6656) { int b = bid - 2048; src = kern; dst = g_kernT; ld = 3072; K = 1536; nb = b % 96; kb = b / 96; }
    else                 { int b = bid - 6656; src = rker; dst = g_rkerT; ld = 3072; K = 1024; nb = b % 96; kb = b / 96; }

    __shared__ float t[32][33];
    const int tx = threadIdx.x, ty = threadIdx.y;
    const int n0 = nb * 32, k0 = kb * 32;
    #pragma unroll
    for (int i = 0; i < 32; i += 8)
        t[ty + i][tx] = src[(size_t)(k0 + ty + i) * ld + n0 + tx];
    __syncthreads();
    #pragma unroll
    for (int i = 0; i < 32; i += 8)
        dst[(size_t)(n0 + ty + i) * K + k0 + tx] = tf32r(t[tx][ty + i]);
}

// ---------------- GEMM: 128x256 (or dual 256x256) tile, cp.async pipeline ----------------
enum { EP_STORE = 0, EP_BIAS = 1, EP_ATT = 2 };

// template params: EMODE; DUAL (0: one 128-row block, 1: two blocks sharing B);
// TKC: K per sync round (32 or 64); NST: pipeline stages.
// stage layout: [A0 halves][A1 halves (if DUAL)][B halves]
// A tile half = 16KB, B half = 32KB, HALFS = TKC/32.
template<int EMODE, int DUAL, int TKC, int NST>
__global__ __launch_bounds__(256)
void tgemm_kernel(const float* __restrict__ A, int lda,
                  const float* __restrict__ Bt, int ldb, int nK,
                  float* __restrict__ C, int ldc,
                  const float* __restrict__ hWa, const float* __restrict__ Va,
                  const float* __restrict__ bias)
{
    extern __shared__ char smc[];
    const int tid = threadIdx.x;
    const int row0 = blockIdx.y * (DUAL ? 2 * TM : TM);
    const int col0 = blockIdx.x * TN;

    constexpr int HALFS   = TKC / 32;
    constexpr int NTILE   = DUAL ? 2 : 1;
    constexpr int A_BYTES = TM * TKC * 4;            // per A tile
    constexpr int B_OFF   = NTILE * A_BYTES;         // B region offset in stage
    constexpr int STAGE   = NTILE * A_BYTES + TN * TKC * 4;
    constexpr int KQ      = TKC / 4;                 // 16B units along K
    constexpr int NA      = KQ / 2;                  // A 16B copies per thread per tile
    constexpr int NB      = KQ;                      // B 16B copies per thread
    constexpr int TMEMC   = DUAL ? 512 : 256;

#if HAS_TCGEN05
    const uint32_t sb  = smem_u32(smc);
    const int wid = tid >> 5;
    const int lid = tid & 31;
    const uint32_t ctrl = sb + NST * STAGE;

    if (wid == 0) { TCG_ALLOC(ctrl, TMEMC); TCG_RELINQ(); }
    if (tid == 0) {
        #pragma unroll
        for (int s = 0; s < NST; ++s) MBAR_INIT(ctrl + 8 + 8 * s, 1);
    }
    __syncthreads();
    uint32_t tmem;
    asm volatile("ld.shared.b32 %0, [%1];" : "=r"(tmem) : "r"(ctrl));

    const uint32_t idesc = (1u << 4) | (2u << 7) | (2u << 10)
                         | ((TN / 8) << 17) | ((TM / 16) << 24);

    uint32_t phbits = 0;
    int sP = 0, sC = 0;
    const int itMax = nK + NST - 1;
    for (int it = 0; it < itMax; ++it) {
        if (it < nK) {
            if (it >= NST) {
                mbar_wait(ctrl + 8 + 8 * sP, (phbits >> sP) & 1u);
                phbits ^= 1u << sP;
            }
            const int k0 = it * TKC;
            const uint32_t sBase = sb + sP * STAGE;
            #pragma unroll
            for (int t = 0; t < NTILE; ++t) {
                #pragma unroll
                for (int i = 0; i < NA; ++i) {
                    const int slot = i * 256 + tid;
                    const int r = slot / KQ, kq = slot % KQ;
                    CP_ASYNC16(sBase + t * A_BYTES + (kq >> 3) * 16384
                                     + SW128(r * 128 + (kq & 7) * 16),
                               &A[(size_t)(row0 + t * TM + r) * lda + k0 + kq * 4]);
                }
            }
            #pragma unroll
            for (int i = 0; i < NB; ++i) {
                const int slot = i * 256 + tid;
                const int r = slot / KQ, kq = slot % KQ;
                CP_ASYNC16(sBase + B_OFF + (kq >> 3) * 32768
                                 + SW128(r * 128 + (kq & 7) * 16),
                           &Bt[(size_t)(col0 + r) * ldb + k0 + kq * 4]);
            }
            sP = (sP + 1 == NST) ? 0 : sP + 1;
        }
        CP_COMMIT();
        const int j = it - (NST - 1);
        if (j >= 0) {
            asm volatile("cp.async.wait_group %0;" :: "n"(NST - 1) : "memory");
            __syncthreads();
            if (tid == 0) {
                FENCE_ASYNC();
                const uint32_t sBase = sb + sC * STAGE;
                #pragma unroll
                for (int half = 0; half < HALFS; ++half) {
                    const uint64_t bd = mk_desc(sBase + B_OFF + half * 32768);
                    #pragma unroll
                    for (int t = 0; t < NTILE; ++t) {
                        const uint64_t ad = mk_desc(sBase + t * A_BYTES + half * 16384);
                        #pragma unroll
                        for (int ss = 0; ss < 4; ++ss)
                            mma_tf32_ss(tmem + t * 256, ad + ss * 2, bd + ss * 2, idesc,
                                        (j > 0 || half > 0 || ss > 0) ? 1u : 0u);
                    }
                }
                TCG_COMMIT(ctrl + 8 + 8 * sC);
            }
            sC = (sC + 1 == NST) ? 0 : sC + 1;
        }
    }
    {
        const int sl = (nK - 1) % NST;
        mbar_wait(ctrl + 8 + 8 * sl, (phbits >> sl) & 1u);
    }
    TCG_FENCE_AFTER();

    // ---- epilogue: 8 warps, two column halves, NTILE row blocks ----
    const int sp = wid & 3;
    const int hf = wid >> 2;

    #pragma unroll
    for (int rb = 0; rb < NTILE; ++rb) {
        const int m = row0 + rb * TM + sp * 32 + lid;
        const uint32_t tb = tmem + rb * 256;
        if (EMODE == EP_ATT) {
            const int b = m >> 6;
            const float* hrow = hWa + (size_t)b * UDIM;
            float s = 0.f;
            #pragma unroll
            for (int c = 0; c < 4; ++c) {
                const int cc = hf * 4 + c;
                uint32_t regs[32];
                tmem_ld32(regs, tb + cc * 32);
                TCG_WAIT_LD();
                const int jj0 = col0 + cc * 32;
                #pragma unroll
                for (int j2 = 0; j2 < 32; ++j2)
                    s += tanhf(__uint_as_float(regs[j2]) + hrow[jj0 + j2]) * Va[jj0 + j2];
            }
            float* sm = reinterpret_cast<float*>(smc);
            __syncthreads();
            sm[wid * 32 + lid] = s;
            __syncthreads();
            if (wid < 4)
                C[(size_t)m * NBX_ATT + blockIdx.x] = sm[wid * 32 + lid] + sm[(wid + 4) * 32 + lid];
        } else {
            #pragma unroll
            for (int c = 0; c < 4; ++c) {
                const int cc = hf * 4 + c;
                uint32_t regs[32];
                tmem_ld32(regs, tb + cc * 32);
                TCG_WAIT_LD();
                const int jj0 = col0 + cc * 32;
                #pragma unroll
                for (int j2 = 0; j2 < 32; j2 += 4) {
                    float4 o;
                    o.x = __uint_as_float(regs[j2 + 0]);
                    o.y = __uint_as_float(regs[j2 + 1]);
                    o.z = __uint_as_float(regs[j2 + 2]);
                    o.w = __uint_as_float(regs[j2 + 3]);
                    if (EMODE == EP_BIAS) {
                        o.x += bias[jj0 + j2 + 0]; o.y += bias[jj0 + j2 + 1];
                        o.z += bias[jj0 + j2 + 2]; o.w += bias[jj0 + j2 + 3];
                    }
                    *reinterpret_cast<float4*>(&C[(size_t)m * ldc + jj0 + j2]) = o;
                }
            }
        }
    }
    TCG_FENCE_BEFORE();
    __syncthreads();
    if (wid == 0) TCG_DEALLOC(tmem, TMEMC);

#else
    // ============ FFMA fallback (plain-sm_103 pass; dead code on GB300) ============
    float* Bs = reinterpret_cast<float*>(smc);
    const int Ktot = nK * TKC;
    for (int rb = 0; rb < NTILE; ++rb) {
        const int m = row0 + rb * TM + (tid & 127);
        float s_att = 0.f;
        for (int nc = 0; nc < 4; ++nc) {
            float acc[64];
            #pragma unroll
            for (int j = 0; j < 64; ++j) acc[j] = 0.f;
            for (int kt = 0; kt < Ktot; kt += 32) {
                for (int i = tid; i < 32 * 64; i += 256) {
                    const int kk = i & 31, j = i >> 5;
                    Bs[kk * 64 + j] = Bt[(size_t)(col0 + nc * 64 + j) * ldb + kt + kk];
                }
                __syncthreads();
                if (tid < 128) {
                    float av[32];
                    #pragma unroll
                    for (int q = 0; q < 32; q += 4) {
                        float4 v = *reinterpret_cast<const float4*>(&A[(size_t)m * lda + kt + q]);
                        av[q] = v.x; av[q + 1] = v.y; av[q + 2] = v.z; av[q + 3] = v.w;
                    }
                    #pragma unroll 4
                    for (int kk = 0; kk < 32; ++kk) {
                        const float a = av[kk];
                        #pragma unroll
                        for (int j = 0; j < 64; ++j)
                            acc[j] = fmaf(a, Bs[kk * 64 + j], acc[j]);
                    }
                }
                __syncthreads();
            }
            if (tid < 128) {
                const int jj0 = col0 + nc * 64;
                if (EMODE == EP_ATT) {
                    const int b = m >> 6;
                    for (int j = 0; j < 64; ++j)
                        s_att += tanhf(acc[j] + hWa[(size_t)b * UDIM + jj0 + j]) * Va[jj0 + j];
                } else {
                    for (int j = 0; j < 64; ++j) {
                        float o = acc[j];
                        if (EMODE == EP_BIAS) o += bias[jj0 + j];
                        C[(size_t)m * ldc + jj0 + j] = o;
                    }
                }
            }
        }
        if (EMODE == EP_ATT && tid < 128)
            C[(size_t)m * NBX_ATT + blockIdx.x] = s_att;
        __syncthreads();
    }
#endif
}

// ---------------- softmax over T + context; alpha -> out, c_t -> g_x ----------------
__global__ __launch_bounds__(256)
void attn_kernel(const float* __restrict__ E, float* __restrict__ out)
{
    const int b   = blockIdx.x;
    const int tid = threadIdx.x;
    __shared__ float alpha[TLEN];

    if (tid < TLEN) {
        const float* ep = g_epart + (size_t)(b * TLEN + tid) * NBX_ATT;
        float e = 0.f;
        #pragma unroll
        for (int p = 0; p < NBX_ATT; ++p) e += ep[p];
        alpha[tid] = e;
    }
    __syncthreads();
    if (tid < 32) {
        float v0 = alpha[tid], v1 = alpha[tid + 32];
        float mx = fmaxf(v0, v1);
        #pragma unroll
        for (int off = 16; off > 0; off >>= 1)
            mx = fmaxf(mx, __shfl_xor_sync(0xffffffffu, mx, off));
        float e0 = expf(v0 - mx), e1 = expf(v1 - mx);
        float s = e0 + e1;
        #pragma unroll
        for (int off = 16; off > 0; off >>= 1)
            s += __shfl_xor_sync(0xffffffffu, s, off);
        float inv = 1.f / s;
        alpha[tid]      = e0 * inv;
        alpha[tid + 32] = e1 * inv;
    }
    __syncthreads();
    if (tid < TLEN)
        out[(size_t)b * 1088 + tid] = alpha[tid];

    const float* Eb = E + (size_t)b * TLEN * EDIM;
    float a0 = 0.f, a1 = 0.f, a2 = 0.f, a3 = 0.f;
    for (int t = 0; t < TLEN; ++t) {
        const float w = alpha[t];
        const float* row = Eb + (size_t)t * EDIM;
        a0 = fmaf(w, row[tid +   0], a0);
        a1 = fmaf(w, row[tid + 256], a1);
        a2 = fmaf(w, row[tid + 512], a2);
        a3 = fmaf(w, row[tid + 768], a3);
    }
    float* xr = g_x + (size_t)b * (XDIM + EDIM) + XDIM;
    xr[tid +   0] = tf32r(a0);
    xr[tid + 256] = tf32r(a1);
    xr[tid + 512] = tf32r(a2);
    xr[tid + 768] = tf32r(a3);
}

// ---------------- gates: z, r; store z and tf32(r*h) ----------------
__global__ __launch_bounds__(256)
void gates_kernel(const float* __restrict__ h)
{
    const int idx = blockIdx.x * blockDim.x + threadIdx.x;
    if (idx >= BSZ * UDIM) return;
    const int m = idx >> 10;
    const int j = idx & 1023;
    const float* G1 = g_G1 + (size_t)m * 3 * UDIM;
    const float* G2 = g_G2 + (size_t)m * 2 * UDIM;
    float z = fminf(fmaxf(0.2f * (G1[j]        + G2[j])        + 0.5f, 0.f), 1.f);
    float r = fminf(fmaxf(0.2f * (G1[j + 1024] + G2[j + 1024]) + 0.5f, 0.f), 1.f);
    g_z[idx]  = z;
    g_rh[idx] = tf32r(r * h[idx]);
}

// ---------------- final: h_new -> out ----------------
__global__ __launch_bounds__(256)
void gru_final_kernel(const float* __restrict__ h, float* __restrict__ out)
{
    const int idx = blockIdx.x * blockDim.x + threadIdx.x;
    if (idx >= BSZ * UDIM) return;
    const int m = idx >> 10;
    const int j = idx & 1023;
    float hh = tanhf(g_G1[(size_t)m * 3 * UDIM + 2048 + j] + g_Ghh[idx]);
    float z  = g_z[idx];
    out[(size_t)m * 1088 + 64 + j] = z * h[idx] + (1.f - z) * hh;
}

// ---------------- launch ----------------
// single-row config: TKC=64, NST=2 -> stage 96KB, total 2*96KB+64
// dual-row  config: TKC=32, NST=3 -> stage 64KB, total 3*64KB+64
#define SMEM_SINGLE (2 * 98304 + 64)
#define SMEM_DUAL   (3 * 65536 + 64)

extern "C" void kernel_launch(void* const* d_in, const int* in_sizes, int n_in,
                              void* d_out, int out_size)
{
    (void)in_sizes; (void)n_in; (void)out_size;
    const float* inputs = (const float*)d_in[0];
    const float* h      = (const float*)d_in[1];
    const float* E      = (const float*)d_in[2];
    const float* kern   = (const float*)d_in[3];
    const float* rker   = (const float*)d_in[4];
    const float* bias   = (const float*)d_in[5];
    const float* Wa     = (const float*)d_in[6];
    const float* Va     = (const float*)d_in[7];
    float* out = (float*)d_out;

    float *tanhE, *tanhH, *h32, *xbuf, *hWa, *epart, *G1, *G2, *rh, *Ghh;
    float *WaTlo, *WaThi, *kernT, *rkerT;
    cudaGetSymbolAddress((void**)&tanhE, g_tanhE);
    cudaGetSymbolAddress((void**)&tanhH, g_tanh_h);
    cudaGetSymbolAddress((void**)&h32,   g_h32);
    cudaGetSymbolAddress((void**)&xbuf,  g_x);
    cudaGetSymbolAddress((void**)&hWa,   g_hWa);
    cudaGetSymbolAddress((void**)&epart, g_epart);
    cudaGetSymbolAddress((void**)&G1,    g_G1);
    cudaGetSymbolAddress((void**)&G2,    g_G2);
    cudaGetSymbolAddress((void**)&rh,    g_rh);
    cudaGetSymbolAddress((void**)&Ghh,   g_Ghh);
    cudaGetSymbolAddress((void**)&WaTlo, g_WaT_lo);
    cudaGetSymbolAddress((void**)&WaThi, g_WaT_hi);
    cudaGetSymbolAddress((void**)&kernT, g_kernT);
    cudaGetSymbolAddress((void**)&rkerT, g_rkerT);

    cudaFuncSetAttribute(tgemm_kernel<EP_STORE, 0, 64, 2>, cudaFuncAttributeMaxDynamicSharedMemorySize, SMEM_SINGLE);
    cudaFuncSetAttribute(tgemm_kernel<EP_BIAS,  0, 64, 2>, cudaFuncAttributeMaxDynamicSharedMemorySize, SMEM_SINGLE);
    cudaFuncSetAttribute(tgemm_kernel<EP_ATT,   1, 32, 3>, cudaFuncAttributeMaxDynamicSharedMemorySize, SMEM_DUAL);

    // [0] weight transposes (tf32-rounded)
    transpose_all_kernel<<<9728, dim3(32, 8)>>>(Wa, kern, rker);

    // [1] tanh(E), tf32-rounded
    const int n4 = BSZ * TLEN * EDIM / 4;
    tanh4_kernel<<<n4 / 256, 256>>>((const float4*)E, (float4*)tanhE, n4);

    // [2] prep: tf32(h), tf32(tanh h), g_x[:, :512]
    prep_kernel<<<(BSZ * UDIM + 255) / 256, 256>>>(h, inputs);

    // [3] hWa = tanh(h) @ Wa[:U]            M=512  N=1024 K=1024 (nK=16)
    tgemm_kernel<EP_STORE, 0, 64, 2><<<dim3(4, 4), 256, SMEM_SINGLE>>>(
        tanhH, UDIM, WaTlo, UDIM, 16, hWa, UDIM, nullptr, nullptr, nullptr);

    // [4] attention GEMM + fused e-partials  M=32768 N=1024 K=1024
    //     dual-row CTAs: grid (4, 128), each CTA does 256 M rows sharing its B tile
    tgemm_kernel<EP_ATT, 1, 32, 3><<<dim3(NBX_ATT, 128), 256, SMEM_DUAL>>>(
        tanhE, EDIM, WaThi, UDIM, 32, epart, 0, hWa, Va, nullptr);

    // [5] softmax + alpha -> out, c_t -> g_x
    attn_kernel<<<BSZ, 256>>>(E, out);

    // [6] G1 = x @ kern + bias               M=512  N=3072 K=1536 (nK=24)
    tgemm_kernel<EP_BIAS, 0, 64, 2><<<dim3(12, 4), 256, SMEM_SINGLE>>>(
        xbuf, XDIM + EDIM, kernT, XDIM + EDIM, 24, G1, 3 * UDIM, nullptr, nullptr, bias);

    // [7] G2 = h @ rker[:, :2048]            M=512  N=2048 K=1024 (nK=16)
    tgemm_kernel<EP_STORE, 0, 64, 2><<<dim3(8, 4), 256, SMEM_SINGLE>>>(
        h32, UDIM, rkerT, UDIM, 16, G2, 2 * UDIM, nullptr, nullptr, nullptr);

    // [8] gates
    gates_kernel<<<(BSZ * UDIM + 255) / 256, 256>>>(h);

    // [9] Ghh = (r*h) @ rker[:, 2048:]       M=512  N=1024 K=1024 (nK=16)
    tgemm_kernel<EP_STORE, 0, 64, 2><<<dim3(4, 4), 256, SMEM_SINGLE>>>(
        rh, UDIM, rkerT + (size_t)2048 * UDIM, UDIM, 16, Ghh, UDIM, nullptr, nullptr, nullptr);

    // [10] h_new
    gru_final_kernel<<<(BSZ * UDIM + 255) / 256, 256>>>(h, out);
}